// round 4
// baseline (speedup 1.0000x reference)
#include <cuda_runtime.h>
#include <cuda.h>
#include <math.h>

#define B_DIM 4096
#define K_DIM 512
#define T_DIM 30
#define WPS   4                     // warps per sample
#define CPL   (K_DIM / (32 * WPS))  // 4 candidates per lane
#define SPC   2                     // samples per CTA
#define NTH   256
#define GRID_DIM (B_DIM / SPC)      // 2048 CTAs
#define ROWS_PER_CTA (SPC * K_DIM)  // 1024
#define TMA_BOX_ROWS 256
#define NUM_TMA (ROWS_PER_CTA / TMA_BOX_ROWS)   // 4
#define MAX_GUESSES 6
#define MISS_THRESH 2.0f

// Scratch (device globals; no runtime allocation)
__device__ float g_loss[B_DIM];
__device__ unsigned int g_cnt = 0;

__device__ __forceinline__ unsigned sortable(float x) {
    unsigned u = __float_as_uint(x);
    return u ^ (unsigned)(((int)u >> 31) | 0x80000000);
}

__device__ __forceinline__ unsigned smem_u32(const void* p) {
    return (unsigned)__cvta_generic_to_shared(p);
}

__device__ __forceinline__ void mbar_wait_parity(unsigned mbar, unsigned parity) {
    asm volatile(
        "{\n\t.reg .pred P;\n\t"
        "WAIT_%=:\n\t"
        "mbarrier.try_wait.parity.shared.b64 P, [%0], %1, 0x989680;\n\t"
        "@P bra.uni DONE_%=;\n\t"
        "bra.uni WAIT_%=;\n\t"
        "DONE_%=:\n\t}"
        :: "r"(mbar), "r"(parity) : "memory");
}

// ---------------------------------------------------------------------------
// Shared per-sample compute body (endpoints passed as c[], o[] in registers)
// ---------------------------------------------------------------------------
struct SampleSmem {
    float    sum[SPC][WPS][3];
    unsigned top[SPC][WPS][MAX_GUESSES];
    unsigned minf[SPC][WPS];
};

__device__ __forceinline__ void compute_sample(
    int b, int s, int ws, int lane,
    const float2 c[CPL], const float o[CPL], float2 g, float sc,
    SampleSmem* sm)
{
    float    f[CPL];
    unsigned os[CPL];
    float zs = 0.f, zo = 0.f, ss = 0.f;
    #pragma unroll
    for (int j = 0; j < CPL; j++) {
        const float dx = c[j].x - g.x;
        const float dy = c[j].y - g.y;
        f[j] = sc * sqrtf(fmaf(dx, dx, dy * dy));
        const float ef = expf(-f[j]);
        zs += ef;
        ss  = fmaf(ef, o[j], ss);
        zo += expf(o[j]);
        os[j] = sortable(o[j]);
    }
    #pragma unroll
    for (int off = 16; off; off >>= 1) {
        zs += __shfl_xor_sync(0xffffffffu, zs, off);
        zo += __shfl_xor_sync(0xffffffffu, zo, off);
        ss += __shfl_xor_sync(0xffffffffu, ss, off);
    }
    if (lane == 0) {
        sm->sum[s][ws][0] = zs; sm->sum[s][ws][1] = zo; sm->sum[s][ws][2] = ss;
    }

    unsigned t0 = 0, t1 = 0, t2 = 0, t3 = 0;
    #pragma unroll
    for (int j = 0; j < CPL; j++) {
        unsigned x = os[j], a;
        a = max(t0, x); x = min(t0, x); t0 = a;
        a = max(t1, x); x = min(t1, x); t1 = a;
        a = max(t2, x); x = min(t2, x); t2 = a;
        t3 = max(t3, x);
    }
    #pragma unroll
    for (int r = 0; r < MAX_GUESSES; r++) {
        const unsigned m = __reduce_max_sync(0xffffffffu, t0);
        if (lane == 0) sm->top[s][ws][r] = m;
        if (t0 == m) { t0 = t1; t1 = t2; t2 = t3; t3 = 0; }
    }
    __syncthreads();

    unsigned m0 = 0, m1 = 0, m2 = 0, m3 = 0, m4 = 0, m5 = 0;
    #pragma unroll
    for (int w = 0; w < WPS; w++) {
        #pragma unroll
        for (int r = 0; r < MAX_GUESSES; r++) {
            unsigned x = sm->top[s][w][r], a;
            a = max(m0, x); x = min(m0, x); m0 = a;
            a = max(m1, x); x = min(m1, x); m1 = a;
            a = max(m2, x); x = min(m2, x); m2 = a;
            a = max(m3, x); x = min(m3, x); m3 = a;
            a = max(m4, x); x = min(m4, x); m4 = a;
            m5 = max(m5, x);
        }
    }
    const unsigned theta = m5;

    float minf = 3.4e38f;
    #pragma unroll
    for (int j = 0; j < CPL; j++)
        if (os[j] >= theta) minf = fminf(minf, f[j]);
    const unsigned mfb = __reduce_min_sync(0xffffffffu, __float_as_uint(minf));
    if (lane == 0) sm->minf[s][ws] = mfb;
    __syncthreads();

    if (ws == 0 && lane == 0) {
        float Zs = 0.f, Zo = 0.f, Ss = 0.f;
        unsigned mn = 0xffffffffu;
        #pragma unroll
        for (int w = 0; w < WPS; w++) {
            Zs += sm->sum[s][w][0];
            Zo += sm->sum[s][w][1];
            Ss += sm->sum[s][w][2];
            mn  = min(mn, sm->minf[s][w]);
        }
        const float minF = __uint_as_float(mn);
        const float cls  = logf(Zo) - Ss / Zs;
        g_loss[b] = cls + fmaxf(minF - MISS_THRESH, 0.0f);
    }
}

__device__ __forceinline__ void tail_reduce(float* out, int lane, int wid) {
    __shared__ bool  s_last;
    __shared__ float sm_red[NTH / 32];
    __syncthreads();
    if (threadIdx.x == 0) {
        __threadfence();
        const unsigned p = atomicAdd(&g_cnt, 1u);
        s_last = (p == (unsigned)(GRID_DIM - 1));
    }
    __syncthreads();
    if (s_last) {
        float acc = 0.f;
        #pragma unroll
        for (int i = 0; i < B_DIM / NTH; i++)
            acc += __ldcg(&g_loss[threadIdx.x + i * NTH]);
        #pragma unroll
        for (int off = 16; off; off >>= 1)
            acc += __shfl_xor_sync(0xffffffffu, acc, off);
        if (lane == 0) sm_red[wid] = acc;
        __syncthreads();
        if (threadIdx.x < 32) {
            acc = (threadIdx.x < NTH / 32) ? sm_red[threadIdx.x] : 0.f;
            #pragma unroll
            for (int off = 4; off; off >>= 1)
                acc += __shfl_xor_sync(0xffffffffu, acc, off);
            if (threadIdx.x == 0) {
                out[0] = acc * (1.0f / (float)B_DIM);
                g_cnt = 0;
            }
        }
    }
}

// ---------------------------------------------------------------------------
// TMA path: endpoint gather through L2_PROMOTION_NONE descriptor
// ---------------------------------------------------------------------------
__global__ __launch_bounds__(NTH)
void score_classify_tma(const float* __restrict__ out_scores,
                        const float* __restrict__ pred_gt,
                        const float* __restrict__ scales,
                        float* __restrict__ out,
                        const __grid_constant__ CUtensorMap tmap)
{
    const int lane = threadIdx.x & 31;
    const int wid  = threadIdx.x >> 5;
    const int s    = wid / WPS;
    const int ws   = wid % WPS;
    const int b    = blockIdx.x * SPC + s;

    __shared__ alignas(128) float4 tile[ROWS_PER_CTA];   // 16KB: one 16B box/row
    __shared__ alignas(8) unsigned long long mbar_store;
    __shared__ SampleSmem sm;

    const unsigned mbar = smem_u32(&mbar_store);
    const unsigned tdst = smem_u32(&tile[0]);

    if (threadIdx.x == 0) {
        asm volatile("mbarrier.init.shared.b64 [%0], 1;" :: "r"(mbar) : "memory");
        asm volatile("fence.proxy.async.shared::cta;" ::: "memory");
    }
    __syncthreads();
    if (threadIdx.x == 0) {
        asm volatile("mbarrier.arrive.expect_tx.shared.b64 _, [%0], %1;"
                     :: "r"(mbar), "r"((unsigned)(ROWS_PER_CTA * 16)) : "memory");
        const int row0 = blockIdx.x * ROWS_PER_CTA;
        #pragma unroll
        for (int i = 0; i < NUM_TMA; i++) {
            asm volatile(
                "cp.async.bulk.tensor.2d.shared::cta.global.tile.mbarrier::complete_tx::bytes "
                "[%0], [%1, {%2, %3}], [%4];"
                :: "r"(tdst + i * TMA_BOX_ROWS * 16), "l"(&tmap),
                   "r"(0), "r"(row0 + i * TMA_BOX_ROWS), "r"(mbar)
                : "memory");
        }
    }

    // overlap: coalesced loads while TMA is in flight
    const float2 g  = *reinterpret_cast<const float2*>(
        pred_gt + ((size_t)b * T_DIM + (T_DIM - 1)) * 2);
    const float  sc = scales[b];
    const float* ob = out_scores + (size_t)b * K_DIM;
    float o[CPL];
    #pragma unroll
    for (int j = 0; j < CPL; j++)
        o[j] = ob[(ws * CPL + j) * 32 + lane];

    mbar_wait_parity(mbar, 0);

    float2 c[CPL];
    #pragma unroll
    for (int j = 0; j < CPL; j++) {
        const int k = (ws * CPL + j) * 32 + lane;
        const float4 e = tile[s * K_DIM + k];   // endpoint in .z,.w
        c[j] = make_float2(e.z, e.w);
    }

    compute_sample(b, s, ws, lane, c, o, g, sc, &sm);
    tail_reduce(out, lane, wid);
}

// ---------------------------------------------------------------------------
// Fallback path: direct LDG gather (identical to R3)
// ---------------------------------------------------------------------------
__global__ __launch_bounds__(NTH)
void score_classify_ldg(const float* __restrict__ out_scores,
                        const float* __restrict__ pred_cand,
                        const float* __restrict__ pred_gt,
                        const float* __restrict__ scales,
                        float* __restrict__ out)
{
    const int lane = threadIdx.x & 31;
    const int wid  = threadIdx.x >> 5;
    const int s    = wid / WPS;
    const int ws   = wid % WPS;
    const int b    = blockIdx.x * SPC + s;

    __shared__ SampleSmem sm;

    const float2 g  = *reinterpret_cast<const float2*>(
        pred_gt + ((size_t)b * T_DIM + (T_DIM - 1)) * 2);
    const float  sc = scales[b];
    const float* ob = out_scores + (size_t)b * K_DIM;
    const float* cb = pred_cand + (((size_t)b * K_DIM) * T_DIM + (T_DIM - 1)) * 2;

    float2 c[CPL];
    float  o[CPL];
    #pragma unroll
    for (int j = 0; j < CPL; j++) {
        const int k = (ws * CPL + j) * 32 + lane;
        o[j] = ob[k];
        c[j] = *reinterpret_cast<const float2*>(cb + (size_t)k * (T_DIM * 2));
    }

    compute_sample(b, s, ws, lane, c, o, g, sc, &sm);
    tail_reduce(out, lane, wid);
}

extern "C" void kernel_launch(void* const* d_in, const int* in_sizes, int n_in,
                              void* d_out, int out_size)
{
    const float* out_scores = (const float*)d_in[0];   // (B*K, 1)
    const float* pred_cand  = (const float*)d_in[1];   // (B, K, T, 2)
    const float* pred_gt    = (const float*)d_in[2];   // (B, T, 2)
    const float* scales     = (const float*)d_in[3];   // (B,)
    float* out = (float*)d_out;

    // Encode tensormap: rows = all B*K candidates, 16B window covering the
    // endpoint (row bytes [224,240) of each 240B candidate record).
    bool ok = false;
    alignas(64) CUtensorMap tmap;
    void* sym = nullptr;
    cudaDriverEntryPointQueryResult qs = cudaDriverEntryPointSymbolNotFound;
    if (cudaGetDriverEntryPointByVersion("cuTensorMapEncodeTiled", &sym, 12000,
                                         cudaEnableDefault, &qs) == cudaSuccess &&
        sym != nullptr && qs == cudaDriverEntryPointSuccess) {
        typedef CUresult (*EncodeFn)(
            CUtensorMap*, CUtensorMapDataType, cuuint32_t, void*,
            const cuuint64_t*, const cuuint64_t*, const cuuint32_t*,
            const cuuint32_t*, CUtensorMapInterleave, CUtensorMapSwizzle,
            CUtensorMapL2promotion, CUtensorMapFloatOOBfill);
        EncodeFn enc = (EncodeFn)sym;
        cuuint64_t dims[2]    = {4, (cuuint64_t)B_DIM * K_DIM};
        cuuint64_t strides[1] = {(cuuint64_t)(T_DIM * 2 * sizeof(float))};  // 240
        cuuint32_t box[2]     = {4, TMA_BOX_ROWS};
        cuuint32_t es[2]      = {1, 1};
        void* base = (void*)((const char*)pred_cand + (T_DIM * 2 - 4) * sizeof(float)); // +224
        ok = enc(&tmap, CU_TENSOR_MAP_DATA_TYPE_FLOAT32, 2, base,
                 dims, strides, box, es,
                 CU_TENSOR_MAP_INTERLEAVE_NONE, CU_TENSOR_MAP_SWIZZLE_NONE,
                 CU_TENSOR_MAP_L2_PROMOTION_NONE,
                 CU_TENSOR_MAP_FLOAT_OOB_FILL_NONE) == CUDA_SUCCESS;
    }

    if (ok)
        score_classify_tma<<<GRID_DIM, NTH>>>(out_scores, pred_gt, scales, out, tmap);
    else
        score_classify_ldg<<<GRID_DIM, NTH>>>(out_scores, pred_cand, pred_gt, scales, out);
}